// round 11
// baseline (speedup 1.0000x reference)
#include <cuda_runtime.h>
#include <cstdint>
#include <cstddef>

#define NROWS  65536
#define CIN    1024
#define COUT   1024
#define NCHUNK 1024
#define CHUNK_ROWS (NROWS / NCHUNK)   // 64

// GEMM tiling: CTA 128(M) x 128(N), K staged 128 bytes at a time
#define MT 128
#define NT 128
#define KITER 8                        // 1024 / 128
#define A_STAGE 16384                  // 128*128
#define B_STAGE 16384                  // 128*128
#define STAGE_BYTES (A_STAGE + B_STAGE)  // 32768
#define GSTAGE 3
#define GEMM_SMEM (GSTAGE * STAGE_BYTES) // 98304 (x2 CTAs = 192KB <= 228KB)

// e4m3 encodings of +1 / -1
#define P1 0x38
#define M1 0xB8

// ---------------- device scratch (allocation-free rule) ----------------
__device__ __align__(16) float g_psum[(size_t)NCHUNK * CIN];
__device__ __align__(16) float g_psq [(size_t)NCHUNK * CIN];
__device__ __align__(16) float g_a[CIN];
__device__ __align__(16) float g_c[CIN];
// pre-swizzled (SW128) e4m3 tile blocks: xq = [mtile(512)][kchunk(8)][128][128]
__device__ __align__(1024) unsigned char g_xq[(size_t)NROWS * CIN];
// wq = [ntile(8)][kchunk(8)][128][128]
__device__ __align__(1024) unsigned char g_wq[(size_t)COUT * CIN];

// ---------------- helpers ----------------
__device__ __forceinline__ uint32_t smem_u32(const void* p) {
    return (uint32_t)__cvta_generic_to_shared(p);
}
__device__ __forceinline__ void cp16(uint32_t s, const void* g) {
    asm volatile("cp.async.cg.shared.global [%0], [%1], 16;" :: "r"(s), "l"(g));
}
__device__ __forceinline__ void cp_commit() {
    asm volatile("cp.async.commit_group;" ::: "memory");
}
template <int N> __device__ __forceinline__ void cp_wait() {
    asm volatile("cp.async.wait_group %0;" :: "n"(N) : "memory");
}
__device__ __forceinline__ void ldsm_x4(uint32_t& r0, uint32_t& r1, uint32_t& r2,
                                        uint32_t& r3, uint32_t a) {
    asm volatile("ldmatrix.sync.aligned.m8n8.x4.shared.b16 {%0,%1,%2,%3}, [%4];"
                 : "=r"(r0), "=r"(r1), "=r"(r2), "=r"(r3) : "r"(a));
}
// FP8 QMMA: m16n8k32, e4m3 x e4m3 -> f32
__device__ __forceinline__ void qmma(float* c, const uint32_t* a, uint32_t b0, uint32_t b1) {
    asm volatile(
        "mma.sync.aligned.m16n8k32.row.col.f32.e4m3.e4m3.f32 "
        "{%0,%1,%2,%3}, {%4,%5,%6,%7}, {%8,%9}, {%0,%1,%2,%3};"
        : "+f"(c[0]), "+f"(c[1]), "+f"(c[2]), "+f"(c[3])
        : "r"(a[0]), "r"(a[1]), "r"(a[2]), "r"(a[3]), "r"(b0), "r"(b1));
}
__device__ __forceinline__ uint32_t sw128(uint32_t off) {
    return off ^ ((off >> 3) & 0x70);
}

// ---------------- kernel 1: stats partials + pack_w (fused, independent work) ----------------
__global__ void k_stats_packw(const float* __restrict__ x, const float* __restrict__ W) {
    int t = threadIdx.x;   // 256
    if (blockIdx.x < NCHUNK) {
        int chunk = blockIdx.x;
        const float4* xp = reinterpret_cast<const float4*>(x)
                         + (size_t)chunk * CHUNK_ROWS * (CIN / 4) + t;
        float s0=0.f,s1=0.f,s2=0.f,s3=0.f,q0=0.f,q1=0.f,q2=0.f,q3=0.f;
#pragma unroll 8
        for (int r = 0; r < CHUNK_ROWS; r++) {
            float4 v = xp[(size_t)r * (CIN / 4)];
            s0 += v.x; q0 = fmaf(v.x, v.x, q0);
            s1 += v.y; q1 = fmaf(v.y, v.y, q1);
            s2 += v.z; q2 = fmaf(v.z, v.z, q2);
            s3 += v.w; q3 = fmaf(v.w, v.w, q3);
        }
        size_t base = (size_t)chunk * CIN + t * 4;
        g_psum[base+0]=s0; g_psum[base+1]=s1; g_psum[base+2]=s2; g_psum[base+3]=s3;
        g_psq [base+0]=q0; g_psq [base+1]=q1; g_psq [base+2]=q2; g_psq [base+3]=q3;
    } else {
        int rl = t >> 6;
        int g  = t & 63;
        int row = (blockIdx.x - NCHUNK) * 4 + rl;
        const float4* wr = reinterpret_cast<const float4*>(W + (size_t)row * CIN) + g * 4;
        unsigned char ob[16];
#pragma unroll
        for (int i = 0; i < 4; i++) {
            float4 v = wr[i];
            ob[i*4+0] = (v.x >= 0.f) ? P1 : M1;
            ob[i*4+1] = (v.y >= 0.f) ? P1 : M1;
            ob[i*4+2] = (v.z >= 0.f) ? P1 : M1;
            ob[i*4+3] = (v.w >= 0.f) ? P1 : M1;
        }
        int ntile  = row >> 7;            // 128-row B tiles
        int r      = row & 127;
        int kchunk = g >> 3;
        uint32_t sw = sw128((uint32_t)(r * 128 + (g & 7) * 16));
        size_t base = ((size_t)ntile * 8 + kchunk) * (size_t)(128 * 128);
        *reinterpret_cast<uint4*>(g_wq + base + sw) = *reinterpret_cast<const uint4*>(ob);
    }
}

// ---------------- kernel 2: BN coefficients (parallel 2-level reduction) ----------------
__global__ void k_stats_final(const float* __restrict__ gamma,
                              const float* __restrict__ beta) {
    __shared__ float ps[256], qs[256];
    int t    = threadIdx.x;
    int cl   = t & 15;                  // column within block
    int seg  = t >> 4;                  // chunk segment 0..15
    int col  = blockIdx.x * 16 + cl;
    float s = 0.f, q = 0.f;
    size_t idx = (size_t)(seg * 64) * CIN + col;
#pragma unroll 8
    for (int k = 0; k < 64; k++) {
        s += g_psum[idx];
        q += g_psq [idx];
        idx += CIN;
    }
    ps[t] = s; qs[t] = q;
    __syncthreads();
    if (seg == 0) {
        float S = 0.f, Q = 0.f;
#pragma unroll
        for (int i = 0; i < 16; i++) { S += ps[i * 16 + cl]; Q += qs[i * 16 + cl]; }
        float mu   = S * (1.0f / NROWS);
        float var  = fmaf(-mu, mu, Q * (1.0f / NROWS));
        float rstd = rsqrtf(var + 1e-5f);
        float a    = rstd * gamma[col];
        g_a[col] = a;
        g_c[col] = fmaf(-mu, a, beta[col]);
    }
}

// ---------------- kernel 3: binarize x -> pre-swizzled e4m3 {+1,-1} ----------------
__global__ void k_pack_x(const float* __restrict__ x) {
    int t  = threadIdx.x;      // 256: 4 rows x 64 col-groups of 16
    int rl = t >> 6;
    int g  = t & 63;
    size_t row = (size_t)blockIdx.x * 4 + rl;
    const float4* xr = reinterpret_cast<const float4*>(x + row * CIN) + g * 4;
    const float4* pa = reinterpret_cast<const float4*>(g_a) + g * 4;
    const float4* pc = reinterpret_cast<const float4*>(g_c) + g * 4;
    unsigned char ob[16];
#pragma unroll
    for (int i = 0; i < 4; i++) {
        float4 v = xr[i], a = pa[i], c = pc[i];
        ob[i*4+0] = (fmaf(a.x, v.x, c.x) >= 0.f) ? P1 : M1;
        ob[i*4+1] = (fmaf(a.y, v.y, c.y) >= 0.f) ? P1 : M1;
        ob[i*4+2] = (fmaf(a.z, v.z, c.z) >= 0.f) ? P1 : M1;
        ob[i*4+3] = (fmaf(a.w, v.w, c.w) >= 0.f) ? P1 : M1;
    }
    int mtile  = (int)(row >> 7);
    int mr     = (int)(row & 127);
    int kchunk = g >> 3;
    uint32_t sw = sw128((uint32_t)(mr * 128 + (g & 7) * 16));
    size_t base = ((size_t)mtile * 8 + kchunk) * (size_t)(128 * 128);
    *reinterpret_cast<uint4*>(g_xq + base + sw) = *reinterpret_cast<const uint4*>(ob);
}

// ---------------- kernel 4: FP8 QMMA GEMM + fused epilogue ----------------
// 256 threads / 8 warps; warp tile 64x32; 2 CTAs/SM (reg cap 128)
// Cross-kk double-buffered operand pipeline: each kk's 6 ldsm issue during the
// previous kk's qmma burst, including across the k boundary (mid-iter wait+sync
// makes stage k+1 visible before kk3, so (k+1,kk0) prefetch overlaps kk3 math).
__global__ void __launch_bounds__(256, 2) k_gemm(
    const float* __restrict__ bias, const float* __restrict__ scale,
    const float* __restrict__ alphap, float* __restrict__ out) {
    extern __shared__ __align__(1024) char smem[];
    uint32_t sb = smem_u32(smem);
    int tid = threadIdx.x, wid = tid >> 5, lane = tid & 31;
    int ntile = blockIdx.x & 7;    // consecutive bids share mtile -> A reuse in L2
    int mtile = blockIdx.x >> 3;

    const unsigned char* ga = g_xq + (size_t)mtile * (8 * A_STAGE) + tid * 16;
    const unsigned char* gb = g_wq + (size_t)ntile * (8 * B_STAGE) + tid * 16;

    auto issue = [&](int k) {
        uint32_t d = sb + (uint32_t)(k % GSTAGE) * STAGE_BYTES + tid * 16;
        const unsigned char* as = ga + (size_t)k * A_STAGE;
        const unsigned char* bs = gb + (size_t)k * B_STAGE;
#pragma unroll
        for (int i = 0; i < 4; i++)
            cp16(d + i * 4096, as + i * 4096);
#pragma unroll
        for (int i = 0; i < 4; i++)
            cp16(d + A_STAGE + i * 4096, bs + i * 4096);
        cp_commit();
    };

    float c[4][4][4];
#pragma unroll
    for (int mt = 0; mt < 4; mt++)
#pragma unroll
        for (int nt = 0; nt < 4; nt++)
#pragma unroll
            for (int i = 0; i < 4; i++) c[mt][nt][i] = 0.f;

    issue(0);
    issue(1);

    int warp_m = wid & 1;   // 2 x 64 rows
    int warp_n = wid >> 1;  // 4 x 32 cols

    // hoisted per-lane swizzled base offsets (relative to stage base)
    // sw128(base + kk*32) == sw128(base) ^ (kk<<5): bits 5-6 of base are zero
    uint32_t a_row = (uint32_t)(warp_m * 64 + (lane & 15));
    uint32_t a_kb  = (uint32_t)((lane >> 4) << 4);
    uint32_t b_row = (uint32_t)(warp_n * 32 + (lane & 7) + ((lane & 16) >> 1));
    uint32_t b_kb  = (uint32_t)((lane & 8) << 1);
    uint32_t a_sw[4], b_sw[2];
#pragma unroll
    for (int mt = 0; mt < 4; mt++)
        a_sw[mt] = sw128((a_row + mt * 16) * 128 + a_kb);
#pragma unroll
    for (int pr = 0; pr < 2; pr++)
        b_sw[pr] = sw128((b_row + pr * 16) * 128 + b_kb) + A_STAGE;

    // double-buffered operand fragments (ping-pong, compile-time indices)
    uint32_t af[2][4][4];
    uint32_t bf[2][8];

    auto load_ops = [&](int buf, uint32_t base, uint32_t kx) {
#pragma unroll
        for (int mt = 0; mt < 4; mt++)
            ldsm_x4(af[buf][mt][0], af[buf][mt][1], af[buf][mt][2], af[buf][mt][3],
                    base + (a_sw[mt] ^ kx));
        ldsm_x4(bf[buf][0], bf[buf][1], bf[buf][2], bf[buf][3], base + (b_sw[0] ^ kx));
        ldsm_x4(bf[buf][4], bf[buf][5], bf[buf][6], bf[buf][7], base + (b_sw[1] ^ kx));
    };
    auto do_qmma = [&](int buf) {
#pragma unroll
        for (int pr = 0; pr < 2; pr++)
#pragma unroll
            for (int mt = 0; mt < 4; mt++) {
                qmma(c[mt][pr*2],     af[buf][mt], bf[buf][pr*4 + 0], bf[buf][pr*4 + 1]);
                qmma(c[mt][pr*2 + 1], af[buf][mt], bf[buf][pr*4 + 2], bf[buf][pr*4 + 3]);
            }
    };

    // prologue: stage 0 visible, prime buffer 0 with (0, kk0)
    cp_wait<1>();
    __syncthreads();
    uint32_t stg = sb;
    load_ops(0, stg, 0);

#pragma unroll 1
    for (int k = 0; k < KITER; k++) {
        uint32_t stg_next = (stg + STAGE_BYTES == sb + GSTAGE * STAGE_BYTES)
                          ? sb : stg + STAGE_BYTES;
        load_ops(1, stg, 1u << 5);  do_qmma(0);   // kk0 compute, kk1 prefetch
        load_ops(0, stg, 2u << 5);  do_qmma(1);   // kk1 compute, kk2 prefetch
        load_ops(1, stg, 3u << 5);  do_qmma(0);   // kk2 compute, kk3 prefetch
        if (k + 1 < KITER) {
            cp_wait<0>();                          // group k+1 complete (issued 1 iter ago)
            __syncthreads();                       // stage k+1 visible to all threads
            load_ops(0, stg_next, 0);              // prefetch (k+1, kk0)
            if (k + 2 < KITER) issue(k + 2);
            do_qmma(1);                            // kk3 compute overlaps the above
        } else {
            do_qmma(1);
        }
        stg = stg_next;
    }

    // ---- epilogue: (c + bias) * scale, PReLU ----
    float alpha = __ldg(alphap);
    int row_base = mtile * MT + warp_m * 64 + (lane >> 2);
    int col_base = ntile * NT + warp_n * 32 + 2 * (lane & 3);
#pragma unroll
    for (int nt = 0; nt < 4; nt++) {
        int col = col_base + nt * 8;
        float b0 = __ldg(bias + col),  b1 = __ldg(bias + col + 1);
        float s0 = __ldg(scale + col), s1 = __ldg(scale + col + 1);
#pragma unroll
        for (int mt = 0; mt < 4; mt++) {
            int r0 = row_base + mt * 16;
            float v0 = (c[mt][nt][0] + b0) * s0;
            float v1 = (c[mt][nt][1] + b1) * s1;
            float v2 = (c[mt][nt][2] + b0) * s0;
            float v3 = (c[mt][nt][3] + b1) * s1;
            float2 o0 = make_float2(v0 > 0.f ? v0 : alpha * v0,
                                    v1 > 0.f ? v1 : alpha * v1);
            float2 o1 = make_float2(v2 > 0.f ? v2 : alpha * v2,
                                    v3 > 0.f ? v3 : alpha * v3);
            *reinterpret_cast<float2*>(out + (size_t)r0 * COUT + col) = o0;
            *reinterpret_cast<float2*>(out + (size_t)(r0 + 8) * COUT + col) = o1;
        }
    }
}

// ---------------- launch ----------------
extern "C" void kernel_launch(void* const* d_in, const int* in_sizes, int n_in,
                              void* d_out, int out_size) {
    (void)in_sizes; (void)n_in; (void)out_size;
    const float* x     = (const float*)d_in[0];
    const float* gamma = (const float*)d_in[1];
    const float* beta  = (const float*)d_in[2];
    const float* W     = (const float*)d_in[3];
    const float* b     = (const float*)d_in[4];
    const float* scale = (const float*)d_in[5];
    const float* alpha = (const float*)d_in[6];
    float* out = (float*)d_out;

    cudaFuncSetAttribute(k_gemm, cudaFuncAttributeMaxDynamicSharedMemorySize, GEMM_SMEM);

    k_stats_packw<<<NCHUNK + COUT / 4, 256>>>(x, W);   // 1: stats partials + pack W
    k_stats_final<<<CIN / 16, 256>>>(gamma, beta);     // 2: parallel reduction
    k_pack_x<<<NROWS / 4, 256>>>(x);                   // 3
    k_gemm<<<(NROWS / MT) * (COUT / NT), 256, GEMM_SMEM>>>(b, scale, alpha, out);  // 4 <- profiled slot
}

// round 12
// speedup vs baseline: 1.1080x; 1.1080x over previous
#include <cuda_runtime.h>
#include <cstdint>
#include <cstddef>

#define NROWS  65536
#define CIN    1024
#define COUT   1024
#define NCHUNK 1024
#define CHUNK_ROWS (NROWS / NCHUNK)   // 64

// GEMM tiling: CTA 128(M) x 128(N), K staged 128 bytes at a time
#define MT 128
#define NT 128
#define KITER 8                        // 1024 / 128
#define A_STAGE 16384                  // 128*128
#define B_STAGE 16384                  // 128*128
#define STAGE_BYTES (A_STAGE + B_STAGE)  // 32768
#define GSTAGE 3
#define GEMM_SMEM (GSTAGE * STAGE_BYTES) // 98304

// e4m3 encodings of +1 / -1
#define P1 0x38
#define M1 0xB8

// ---------------- device scratch (allocation-free rule) ----------------
__device__ __align__(16) float g_psum[(size_t)NCHUNK * CIN];
__device__ __align__(16) float g_psq [(size_t)NCHUNK * CIN];
__device__ __align__(16) float g_a[CIN];
__device__ __align__(16) float g_c[CIN];
// pre-swizzled (SW128) e4m3 tile blocks: xq = [mtile(512)][kchunk(8)][128][128]
__device__ __align__(1024) unsigned char g_xq[(size_t)NROWS * CIN];
// wq = [ntile(8)][kchunk(8)][128][128]
__device__ __align__(1024) unsigned char g_wq[(size_t)COUT * CIN];

// ---------------- helpers ----------------
__device__ __forceinline__ uint32_t smem_u32(const void* p) {
    return (uint32_t)__cvta_generic_to_shared(p);
}
__device__ __forceinline__ void cp16(uint32_t s, const void* g) {
    asm volatile("cp.async.cg.shared.global [%0], [%1], 16;" :: "r"(s), "l"(g));
}
__device__ __forceinline__ void cp_commit() {
    asm volatile("cp.async.commit_group;" ::: "memory");
}
template <int N> __device__ __forceinline__ void cp_wait() {
    asm volatile("cp.async.wait_group %0;" :: "n"(N) : "memory");
}
__device__ __forceinline__ void ldsm_x4(uint32_t& r0, uint32_t& r1, uint32_t& r2,
                                        uint32_t& r3, uint32_t a) {
    asm volatile("ldmatrix.sync.aligned.m8n8.x4.shared.b16 {%0,%1,%2,%3}, [%4];"
                 : "=r"(r0), "=r"(r1), "=r"(r2), "=r"(r3) : "r"(a));
}
// FP8 QMMA: m16n8k32, e4m3 x e4m3 -> f32
__device__ __forceinline__ void qmma(float* c, const uint32_t* a, uint32_t b0, uint32_t b1) {
    asm volatile(
        "mma.sync.aligned.m16n8k32.row.col.f32.e4m3.e4m3.f32 "
        "{%0,%1,%2,%3}, {%4,%5,%6,%7}, {%8,%9}, {%0,%1,%2,%3};"
        : "+f"(c[0]), "+f"(c[1]), "+f"(c[2]), "+f"(c[3])
        : "r"(a[0]), "r"(a[1]), "r"(a[2]), "r"(a[3]), "r"(b0), "r"(b1));
}
__device__ __forceinline__ uint32_t sw128(uint32_t off) {
    return off ^ ((off >> 3) & 0x70);
}

// ---------------- kernel 1: stats partials + pack_w (fused, independent work) ----------------
__global__ void k_stats_packw(const float* __restrict__ x, const float* __restrict__ W) {
    int t = threadIdx.x;   // 256
    if (blockIdx.x < NCHUNK) {
        int chunk = blockIdx.x;
        const float4* xp = reinterpret_cast<const float4*>(x)
                         + (size_t)chunk * CHUNK_ROWS * (CIN / 4) + t;
        float s0=0.f,s1=0.f,s2=0.f,s3=0.f,q0=0.f,q1=0.f,q2=0.f,q3=0.f;
#pragma unroll 8
        for (int r = 0; r < CHUNK_ROWS; r++) {
            float4 v = xp[(size_t)r * (CIN / 4)];
            s0 += v.x; q0 = fmaf(v.x, v.x, q0);
            s1 += v.y; q1 = fmaf(v.y, v.y, q1);
            s2 += v.z; q2 = fmaf(v.z, v.z, q2);
            s3 += v.w; q3 = fmaf(v.w, v.w, q3);
        }
        size_t base = (size_t)chunk * CIN + t * 4;
        g_psum[base+0]=s0; g_psum[base+1]=s1; g_psum[base+2]=s2; g_psum[base+3]=s3;
        g_psq [base+0]=q0; g_psq [base+1]=q1; g_psq [base+2]=q2; g_psq [base+3]=q3;
    } else {
        int rl = t >> 6;
        int g  = t & 63;
        int row = (blockIdx.x - NCHUNK) * 4 + rl;
        const float4* wr = reinterpret_cast<const float4*>(W + (size_t)row * CIN) + g * 4;
        unsigned char ob[16];
#pragma unroll
        for (int i = 0; i < 4; i++) {
            float4 v = wr[i];
            ob[i*4+0] = (v.x >= 0.f) ? P1 : M1;
            ob[i*4+1] = (v.y >= 0.f) ? P1 : M1;
            ob[i*4+2] = (v.z >= 0.f) ? P1 : M1;
            ob[i*4+3] = (v.w >= 0.f) ? P1 : M1;
        }
        int ntile  = row >> 7;            // 128-row B tiles
        int r      = row & 127;
        int kchunk = g >> 3;
        uint32_t sw = sw128((uint32_t)(r * 128 + (g & 7) * 16));
        size_t base = ((size_t)ntile * 8 + kchunk) * (size_t)(128 * 128);
        *reinterpret_cast<uint4*>(g_wq + base + sw) = *reinterpret_cast<const uint4*>(ob);
    }
}

// ---------------- kernel 2: BN coefficients (parallel 2-level reduction) ----------------
__global__ void k_stats_final(const float* __restrict__ gamma,
                              const float* __restrict__ beta) {
    __shared__ float ps[256], qs[256];
    int t    = threadIdx.x;
    int cl   = t & 15;                  // column within block
    int seg  = t >> 4;                  // chunk segment 0..15
    int col  = blockIdx.x * 16 + cl;
    float s = 0.f, q = 0.f;
    size_t idx = (size_t)(seg * 64) * CIN + col;
#pragma unroll 8
    for (int k = 0; k < 64; k++) {
        s += g_psum[idx];
        q += g_psq [idx];
        idx += CIN;
    }
    ps[t] = s; qs[t] = q;
    __syncthreads();
    if (seg == 0) {
        float S = 0.f, Q = 0.f;
#pragma unroll
        for (int i = 0; i < 16; i++) { S += ps[i * 16 + cl]; Q += qs[i * 16 + cl]; }
        float mu   = S * (1.0f / NROWS);
        float var  = fmaf(-mu, mu, Q * (1.0f / NROWS));
        float rstd = rsqrtf(var + 1e-5f);
        float a    = rstd * gamma[col];
        g_a[col] = a;
        g_c[col] = fmaf(-mu, a, beta[col]);
    }
}

// ---------------- kernel 3: binarize x -> pre-swizzled e4m3 {+1,-1} ----------------
__global__ void k_pack_x(const float* __restrict__ x) {
    int t  = threadIdx.x;      // 256: 4 rows x 64 col-groups of 16
    int rl = t >> 6;
    int g  = t & 63;
    size_t row = (size_t)blockIdx.x * 4 + rl;
    const float4* xr = reinterpret_cast<const float4*>(x + row * CIN) + g * 4;
    const float4* pa = reinterpret_cast<const float4*>(g_a) + g * 4;
    const float4* pc = reinterpret_cast<const float4*>(g_c) + g * 4;
    unsigned char ob[16];
#pragma unroll
    for (int i = 0; i < 4; i++) {
        float4 v = xr[i], a = pa[i], c = pc[i];
        ob[i*4+0] = (fmaf(a.x, v.x, c.x) >= 0.f) ? P1 : M1;
        ob[i*4+1] = (fmaf(a.y, v.y, c.y) >= 0.f) ? P1 : M1;
        ob[i*4+2] = (fmaf(a.z, v.z, c.z) >= 0.f) ? P1 : M1;
        ob[i*4+3] = (fmaf(a.w, v.w, c.w) >= 0.f) ? P1 : M1;
    }
    int mtile  = (int)(row >> 7);
    int mr     = (int)(row & 127);
    int kchunk = g >> 3;
    uint32_t sw = sw128((uint32_t)(mr * 128 + (g & 7) * 16));
    size_t base = ((size_t)mtile * 8 + kchunk) * (size_t)(128 * 128);
    *reinterpret_cast<uint4*>(g_xq + base + sw) = *reinterpret_cast<const uint4*>(ob);
}

// ---------------- kernel 4: FP8 QMMA GEMM + fused epilogue ----------------
// 256 threads / 8 warps; warp tile 64x32; 1 CTA/SM (255-reg budget: the R11
// cross-kk double-buffered operand pipeline WITHOUT spills).
__global__ void __launch_bounds__(256, 1) k_gemm(
    const float* __restrict__ bias, const float* __restrict__ scale,
    const float* __restrict__ alphap, float* __restrict__ out) {
    extern __shared__ __align__(1024) char smem[];
    uint32_t sb = smem_u32(smem);
    int tid = threadIdx.x, wid = tid >> 5, lane = tid & 31;
    int ntile = blockIdx.x & 7;    // consecutive bids share mtile -> A reuse in L2
    int mtile = blockIdx.x >> 3;

    const unsigned char* ga = g_xq + (size_t)mtile * (8 * A_STAGE) + tid * 16;
    const unsigned char* gb = g_wq + (size_t)ntile * (8 * B_STAGE) + tid * 16;

    auto issue = [&](int k) {
        uint32_t d = sb + (uint32_t)(k % GSTAGE) * STAGE_BYTES + tid * 16;
        const unsigned char* as = ga + (size_t)k * A_STAGE;
        const unsigned char* bs = gb + (size_t)k * B_STAGE;
#pragma unroll
        for (int i = 0; i < 4; i++)
            cp16(d + i * 4096, as + i * 4096);
#pragma unroll
        for (int i = 0; i < 4; i++)
            cp16(d + A_STAGE + i * 4096, bs + i * 4096);
        cp_commit();
    };

    float c[4][4][4];
#pragma unroll
    for (int mt = 0; mt < 4; mt++)
#pragma unroll
        for (int nt = 0; nt < 4; nt++)
#pragma unroll
            for (int i = 0; i < 4; i++) c[mt][nt][i] = 0.f;

    issue(0);
    issue(1);

    int warp_m = wid & 1;   // 2 x 64 rows
    int warp_n = wid >> 1;  // 4 x 32 cols

    // hoisted per-lane swizzled base offsets (relative to stage base)
    // sw128(base + kk*32) == sw128(base) ^ (kk<<5): bits 5-6 of base are zero
    uint32_t a_row = (uint32_t)(warp_m * 64 + (lane & 15));
    uint32_t a_kb  = (uint32_t)((lane >> 4) << 4);
    uint32_t b_row = (uint32_t)(warp_n * 32 + (lane & 7) + ((lane & 16) >> 1));
    uint32_t b_kb  = (uint32_t)((lane & 8) << 1);
    uint32_t a_sw[4], b_sw[2];
#pragma unroll
    for (int mt = 0; mt < 4; mt++)
        a_sw[mt] = sw128((a_row + mt * 16) * 128 + a_kb);
#pragma unroll
    for (int pr = 0; pr < 2; pr++)
        b_sw[pr] = sw128((b_row + pr * 16) * 128 + b_kb) + A_STAGE;

    // double-buffered operand fragments (ping-pong, compile-time indices)
    uint32_t af[2][4][4];
    uint32_t bf[2][8];

    auto load_ops = [&](int buf, uint32_t base, uint32_t kx) {
        // B first: first consumers of the next qmma burst
        ldsm_x4(bf[buf][0], bf[buf][1], bf[buf][2], bf[buf][3], base + (b_sw[0] ^ kx));
        ldsm_x4(bf[buf][4], bf[buf][5], bf[buf][6], bf[buf][7], base + (b_sw[1] ^ kx));
#pragma unroll
        for (int mt = 0; mt < 4; mt++)
            ldsm_x4(af[buf][mt][0], af[buf][mt][1], af[buf][mt][2], af[buf][mt][3],
                    base + (a_sw[mt] ^ kx));
    };
    auto do_qmma = [&](int buf) {
#pragma unroll
        for (int pr = 0; pr < 2; pr++)
#pragma unroll
            for (int mt = 0; mt < 4; mt++) {
                qmma(c[mt][pr*2],     af[buf][mt], bf[buf][pr*4 + 0], bf[buf][pr*4 + 1]);
                qmma(c[mt][pr*2 + 1], af[buf][mt], bf[buf][pr*4 + 2], bf[buf][pr*4 + 3]);
            }
    };

    // prologue: stage 0 visible, prime buffer 0 with (0, kk0)
    cp_wait<1>();
    __syncthreads();
    uint32_t stg = sb;
    load_ops(0, stg, 0);

#pragma unroll 1
    for (int k = 0; k < KITER; k++) {
        uint32_t stg_next = (stg + STAGE_BYTES == sb + GSTAGE * STAGE_BYTES)
                          ? sb : stg + STAGE_BYTES;
        load_ops(1, stg, 1u << 5);  do_qmma(0);   // kk0 compute, kk1 prefetch
        load_ops(0, stg, 2u << 5);  do_qmma(1);   // kk1 compute, kk2 prefetch
        load_ops(1, stg, 3u << 5);  do_qmma(0);   // kk2 compute, kk3 prefetch
        if (k + 1 < KITER) {
            if (k + 2 < KITER) issue(k + 2);       // keep 2-deep cp.async pipeline
            cp_wait<1>();                          // stage k+1 resident
            __syncthreads();
            load_ops(0, stg_next, 0);              // prefetch (k+1, kk0)
            do_qmma(1);                            // kk3 compute overlaps the above
        } else {
            do_qmma(1);
        }
        stg = stg_next;
    }

    // ---- epilogue: (c + bias) * scale, PReLU ----
    float alpha = __ldg(alphap);
    int row_base = mtile * MT + warp_m * 64 + (lane >> 2);
    int col_base = ntile * NT + warp_n * 32 + 2 * (lane & 3);
#pragma unroll
    for (int nt = 0; nt < 4; nt++) {
        int col = col_base + nt * 8;
        float b0 = __ldg(bias + col),  b1 = __ldg(bias + col + 1);
        float s0 = __ldg(scale + col), s1 = __ldg(scale + col + 1);
#pragma unroll
        for (int mt = 0; mt < 4; mt++) {
            int r0 = row_base + mt * 16;
            float v0 = (c[mt][nt][0] + b0) * s0;
            float v1 = (c[mt][nt][1] + b1) * s1;
            float v2 = (c[mt][nt][2] + b0) * s0;
            float v3 = (c[mt][nt][3] + b1) * s1;
            float2 o0 = make_float2(v0 > 0.f ? v0 : alpha * v0,
                                    v1 > 0.f ? v1 : alpha * v1);
            float2 o1 = make_float2(v2 > 0.f ? v2 : alpha * v2,
                                    v3 > 0.f ? v3 : alpha * v3);
            *reinterpret_cast<float2*>(out + (size_t)r0 * COUT + col) = o0;
            *reinterpret_cast<float2*>(out + (size_t)(r0 + 8) * COUT + col) = o1;
        }
    }
}

// ---------------- launch ----------------
extern "C" void kernel_launch(void* const* d_in, const int* in_sizes, int n_in,
                              void* d_out, int out_size) {
    (void)in_sizes; (void)n_in; (void)out_size;
    const float* x     = (const float*)d_in[0];
    const float* gamma = (const float*)d_in[1];
    const float* beta  = (const float*)d_in[2];
    const float* W     = (const float*)d_in[3];
    const float* b     = (const float*)d_in[4];
    const float* scale = (const float*)d_in[5];
    const float* alpha = (const float*)d_in[6];
    float* out = (float*)d_out;

    cudaFuncSetAttribute(k_gemm, cudaFuncAttributeMaxDynamicSharedMemorySize, GEMM_SMEM);

    k_stats_packw<<<NCHUNK + COUT / 4, 256>>>(x, W);   // 1: stats partials + pack W
    k_stats_final<<<CIN / 16, 256>>>(gamma, beta);     // 2: parallel reduction
    k_pack_x<<<NROWS / 4, 256>>>(x);                   // 3
    k_gemm<<<(NROWS / MT) * (COUT / NT), 256, GEMM_SMEM>>>(b, scale, alpha, out);  // 4 <- profiled slot
}

// round 13
// speedup vs baseline: 1.2416x; 1.1206x over previous
#include <cuda_runtime.h>
#include <cuda_fp16.h>
#include <cstdint>
#include <cstddef>

#define NROWS  65536
#define CIN    1024
#define COUT   1024
#define NCHUNK 1024
#define CHUNK_ROWS (NROWS / NCHUNK)   // 64

// GEMM tiling: CTA 128(M) x 128(N), K staged 128 bytes at a time
#define MT 128
#define NT 128
#define KITER 8                        // 1024 / 128
#define A_STAGE 16384                  // 128*128
#define B_STAGE 16384                  // 128*128
#define STAGE_BYTES (A_STAGE + B_STAGE)  // 32768
#define GSTAGE 3
#define GEMM_SMEM (GSTAGE * STAGE_BYTES) // 98304 (x2 CTAs = 192KB <= 228KB)

// e4m3 encodings of +1 / -1
#define P1 0x38
#define M1 0xB8

// ---------------- device scratch (allocation-free rule) ----------------
__device__ __align__(16) float g_psum[(size_t)NCHUNK * CIN];
__device__ __align__(16) float g_psq [(size_t)NCHUNK * CIN];
__device__ __align__(16) float g_a[CIN];
__device__ __align__(16) float g_c[CIN];
// pre-swizzled (SW128) e4m3 tile blocks: xq = [mtile(512)][kchunk(8)][128][128]
__device__ __align__(1024) unsigned char g_xq[(size_t)NROWS * CIN];
// wq = [ntile(8)][kchunk(8)][128][128]
__device__ __align__(1024) unsigned char g_wq[(size_t)COUT * CIN];

// ---------------- helpers ----------------
__device__ __forceinline__ uint32_t smem_u32(const void* p) {
    return (uint32_t)__cvta_generic_to_shared(p);
}
__device__ __forceinline__ void cp16(uint32_t s, const void* g) {
    asm volatile("cp.async.cg.shared.global [%0], [%1], 16;" :: "r"(s), "l"(g));
}
__device__ __forceinline__ void cp_commit() {
    asm volatile("cp.async.commit_group;" ::: "memory");
}
template <int N> __device__ __forceinline__ void cp_wait() {
    asm volatile("cp.async.wait_group %0;" :: "n"(N) : "memory");
}
__device__ __forceinline__ void ldsm_x4(uint32_t& r0, uint32_t& r1, uint32_t& r2,
                                        uint32_t& r3, uint32_t a) {
    asm volatile("ldmatrix.sync.aligned.m8n8.x4.shared.b16 {%0,%1,%2,%3}, [%4];"
                 : "=r"(r0), "=r"(r1), "=r"(r2), "=r"(r3) : "r"(a));
}
// FP8 QMMA with FP16 accumulator: m16n8k32, e4m3 x e4m3 -> f16 (2 c-regs).
// Exact here: all partial sums are integers in [-1024, 1024] (< 2048).
__device__ __forceinline__ void qmma16(uint32_t* c, const uint32_t* a,
                                       uint32_t b0, uint32_t b1) {
    asm volatile(
        "mma.sync.aligned.m16n8k32.row.col.f16.e4m3.e4m3.f16 "
        "{%0,%1}, {%2,%3,%4,%5}, {%6,%7}, {%0,%1};"
        : "+r"(c[0]), "+r"(c[1])
        : "r"(a[0]), "r"(a[1]), "r"(a[2]), "r"(a[3]), "r"(b0), "r"(b1));
}
__device__ __forceinline__ uint32_t sw128(uint32_t off) {
    return off ^ ((off >> 3) & 0x70);
}

// ---------------- kernel 1: stats partials + pack_w (fused, independent work) ----------------
__global__ void k_stats_packw(const float* __restrict__ x, const float* __restrict__ W) {
    int t = threadIdx.x;   // 256
    if (blockIdx.x < NCHUNK) {
        int chunk = blockIdx.x;
        const float4* xp = reinterpret_cast<const float4*>(x)
                         + (size_t)chunk * CHUNK_ROWS * (CIN / 4) + t;
        float s0=0.f,s1=0.f,s2=0.f,s3=0.f,q0=0.f,q1=0.f,q2=0.f,q3=0.f;
#pragma unroll 8
        for (int r = 0; r < CHUNK_ROWS; r++) {
            float4 v = xp[(size_t)r * (CIN / 4)];
            s0 += v.x; q0 = fmaf(v.x, v.x, q0);
            s1 += v.y; q1 = fmaf(v.y, v.y, q1);
            s2 += v.z; q2 = fmaf(v.z, v.z, q2);
            s3 += v.w; q3 = fmaf(v.w, v.w, q3);
        }
        size_t base = (size_t)chunk * CIN + t * 4;
        g_psum[base+0]=s0; g_psum[base+1]=s1; g_psum[base+2]=s2; g_psum[base+3]=s3;
        g_psq [base+0]=q0; g_psq [base+1]=q1; g_psq [base+2]=q2; g_psq [base+3]=q3;
    } else {
        int rl = t >> 6;
        int g  = t & 63;
        int row = (blockIdx.x - NCHUNK) * 4 + rl;
        const float4* wr = reinterpret_cast<const float4*>(W + (size_t)row * CIN) + g * 4;
        unsigned char ob[16];
#pragma unroll
        for (int i = 0; i < 4; i++) {
            float4 v = wr[i];
            ob[i*4+0] = (v.x >= 0.f) ? P1 : M1;
            ob[i*4+1] = (v.y >= 0.f) ? P1 : M1;
            ob[i*4+2] = (v.z >= 0.f) ? P1 : M1;
            ob[i*4+3] = (v.w >= 0.f) ? P1 : M1;
        }
        int ntile  = row >> 7;            // 128-row B tiles
        int r      = row & 127;
        int kchunk = g >> 3;
        uint32_t sw = sw128((uint32_t)(r * 128 + (g & 7) * 16));
        size_t base = ((size_t)ntile * 8 + kchunk) * (size_t)(128 * 128);
        *reinterpret_cast<uint4*>(g_wq + base + sw) = *reinterpret_cast<const uint4*>(ob);
    }
}

// ---------------- kernel 2: BN coefficients (parallel 2-level reduction) ----------------
__global__ void k_stats_final(const float* __restrict__ gamma,
                              const float* __restrict__ beta) {
    __shared__ float ps[256], qs[256];
    int t    = threadIdx.x;
    int cl   = t & 15;                  // column within block
    int seg  = t >> 4;                  // chunk segment 0..15
    int col  = blockIdx.x * 16 + cl;
    float s = 0.f, q = 0.f;
    size_t idx = (size_t)(seg * 64) * CIN + col;
#pragma unroll 8
    for (int k = 0; k < 64; k++) {
        s += g_psum[idx];
        q += g_psq [idx];
        idx += CIN;
    }
    ps[t] = s; qs[t] = q;
    __syncthreads();
    if (seg == 0) {
        float S = 0.f, Q = 0.f;
#pragma unroll
        for (int i = 0; i < 16; i++) { S += ps[i * 16 + cl]; Q += qs[i * 16 + cl]; }
        float mu   = S * (1.0f / NROWS);
        float var  = fmaf(-mu, mu, Q * (1.0f / NROWS));
        float rstd = rsqrtf(var + 1e-5f);
        float a    = rstd * gamma[col];
        g_a[col] = a;
        g_c[col] = fmaf(-mu, a, beta[col]);
    }
}

// ---------------- kernel 3: binarize x -> pre-swizzled e4m3 {+1,-1} ----------------
__global__ void k_pack_x(const float* __restrict__ x) {
    int t  = threadIdx.x;      // 256: 4 rows x 64 col-groups of 16
    int rl = t >> 6;
    int g  = t & 63;
    size_t row = (size_t)blockIdx.x * 4 + rl;
    const float4* xr = reinterpret_cast<const float4*>(x + row * CIN) + g * 4;
    const float4* pa = reinterpret_cast<const float4*>(g_a) + g * 4;
    const float4* pc = reinterpret_cast<const float4*>(g_c) + g * 4;
    unsigned char ob[16];
#pragma unroll
    for (int i = 0; i < 4; i++) {
        float4 v = xr[i], a = pa[i], c = pc[i];
        ob[i*4+0] = (fmaf(a.x, v.x, c.x) >= 0.f) ? P1 : M1;
        ob[i*4+1] = (fmaf(a.y, v.y, c.y) >= 0.f) ? P1 : M1;
        ob[i*4+2] = (fmaf(a.z, v.z, c.z) >= 0.f) ? P1 : M1;
        ob[i*4+3] = (fmaf(a.w, v.w, c.w) >= 0.f) ? P1 : M1;
    }
    int mtile  = (int)(row >> 7);
    int mr     = (int)(row & 127);
    int kchunk = g >> 3;
    uint32_t sw = sw128((uint32_t)(mr * 128 + (g & 7) * 16));
    size_t base = ((size_t)mtile * 8 + kchunk) * (size_t)(128 * 128);
    *reinterpret_cast<uint4*>(g_xq + base + sw) = *reinterpret_cast<const uint4*>(ob);
}

// ---------------- kernel 4: FP8 QMMA (f16 accum) GEMM + fused epilogue ----------------
// 256 threads / 8 warps; warp tile 64x32; 2 CTAs/SM (128-reg cap).
// f16 accumulators (32 regs) leave room for the cross-kk double-buffered
// operand pipeline with NO spills: accum 32 + operands 48 + addressing ~35.
__global__ void __launch_bounds__(256, 2) k_gemm(
    const float* __restrict__ bias, const float* __restrict__ scale,
    const float* __restrict__ alphap, float* __restrict__ out) {
    extern __shared__ __align__(1024) char smem[];
    uint32_t sb = smem_u32(smem);
    int tid = threadIdx.x, wid = tid >> 5, lane = tid & 31;
    int ntile = blockIdx.x & 7;    // consecutive bids share mtile -> A reuse in L2
    int mtile = blockIdx.x >> 3;

    const unsigned char* ga = g_xq + (size_t)mtile * (8 * A_STAGE) + tid * 16;
    const unsigned char* gb = g_wq + (size_t)ntile * (8 * B_STAGE) + tid * 16;

    auto issue = [&](int k) {
        uint32_t d = sb + (uint32_t)(k % GSTAGE) * STAGE_BYTES + tid * 16;
        const unsigned char* as = ga + (size_t)k * A_STAGE;
        const unsigned char* bs = gb + (size_t)k * B_STAGE;
#pragma unroll
        for (int i = 0; i < 4; i++)
            cp16(d + i * 4096, as + i * 4096);
#pragma unroll
        for (int i = 0; i < 4; i++)
            cp16(d + A_STAGE + i * 4096, bs + i * 4096);
        cp_commit();
    };

    // f16 accumulators: c[mt][nt][0] = row r cols {c0,c1}; [1] = row r+8
    uint32_t c[4][4][2];
#pragma unroll
    for (int mt = 0; mt < 4; mt++)
#pragma unroll
        for (int nt = 0; nt < 4; nt++) { c[mt][nt][0] = 0u; c[mt][nt][1] = 0u; }

    issue(0);
    issue(1);

    int warp_m = wid & 1;   // 2 x 64 rows
    int warp_n = wid >> 1;  // 4 x 32 cols

    // hoisted per-lane swizzled base offsets (relative to stage base)
    // sw128(base + kk*32) == sw128(base) ^ (kk<<5): bits 5-6 of base are zero
    uint32_t a_row = (uint32_t)(warp_m * 64 + (lane & 15));
    uint32_t a_kb  = (uint32_t)((lane >> 4) << 4);
    uint32_t b_row = (uint32_t)(warp_n * 32 + (lane & 7) + ((lane & 16) >> 1));
    uint32_t b_kb  = (uint32_t)((lane & 8) << 1);
    uint32_t a_sw[4], b_sw[2];
#pragma unroll
    for (int mt = 0; mt < 4; mt++)
        a_sw[mt] = sw128((a_row + mt * 16) * 128 + a_kb);
#pragma unroll
    for (int pr = 0; pr < 2; pr++)
        b_sw[pr] = sw128((b_row + pr * 16) * 128 + b_kb) + A_STAGE;

    // double-buffered operand fragments (ping-pong, compile-time indices)
    uint32_t af[2][4][4];
    uint32_t bf[2][8];

    auto load_ops = [&](int buf, uint32_t base, uint32_t kx) {
        // B first: first consumers of the next qmma burst
        ldsm_x4(bf[buf][0], bf[buf][1], bf[buf][2], bf[buf][3], base + (b_sw[0] ^ kx));
        ldsm_x4(bf[buf][4], bf[buf][5], bf[buf][6], bf[buf][7], base + (b_sw[1] ^ kx));
#pragma unroll
        for (int mt = 0; mt < 4; mt++)
            ldsm_x4(af[buf][mt][0], af[buf][mt][1], af[buf][mt][2], af[buf][mt][3],
                    base + (a_sw[mt] ^ kx));
    };
    auto do_qmma = [&](int buf) {
#pragma unroll
        for (int pr = 0; pr < 2; pr++)
#pragma unroll
            for (int mt = 0; mt < 4; mt++) {
                qmma16(c[mt][pr*2],     af[buf][mt], bf[buf][pr*4 + 0], bf[buf][pr*4 + 1]);
                qmma16(c[mt][pr*2 + 1], af[buf][mt], bf[buf][pr*4 + 2], bf[buf][pr*4 + 3]);
            }
    };

    // prologue: stage 0 visible, prime buffer 0 with (0, kk0)
    cp_wait<1>();
    __syncthreads();
    uint32_t stg = sb;
    load_ops(0, stg, 0);

#pragma unroll 1
    for (int k = 0; k < KITER; k++) {
        uint32_t stg_next = (stg + STAGE_BYTES == sb + GSTAGE * STAGE_BYTES)
                          ? sb : stg + STAGE_BYTES;
        load_ops(1, stg, 1u << 5);  do_qmma(0);   // kk0 compute, kk1 prefetch
        load_ops(0, stg, 2u << 5);  do_qmma(1);   // kk1 compute, kk2 prefetch
        load_ops(1, stg, 3u << 5);  do_qmma(0);   // kk2 compute, kk3 prefetch
        if (k + 1 < KITER) {
            if (k + 2 < KITER) issue(k + 2);       // keep 2-deep cp.async pipeline
            cp_wait<1>();                          // stage k+1 resident
            __syncthreads();
            load_ops(0, stg_next, 0);              // prefetch (k+1, kk0)
            do_qmma(1);                            // kk3 compute overlaps the above
        } else {
            do_qmma(1);
        }
        stg = stg_next;
    }

    // ---- epilogue: (c + bias) * scale, PReLU (unpack f16x2 accumulators) ----
    float alpha = __ldg(alphap);
    int row_base = mtile * MT + warp_m * 64 + (lane >> 2);
    int col_base = ntile * NT + warp_n * 32 + 2 * (lane & 3);
#pragma unroll
    for (int nt = 0; nt < 4; nt++) {
        int col = col_base + nt * 8;
        float b0 = __ldg(bias + col),  b1 = __ldg(bias + col + 1);
        float s0 = __ldg(scale + col), s1 = __ldg(scale + col + 1);
#pragma unroll
        for (int mt = 0; mt < 4; mt++) {
            int r0 = row_base + mt * 16;
            float2 f0 = __half22float2(*reinterpret_cast<__half2*>(&c[mt][nt][0]));
            float2 f1 = __half22float2(*reinterpret_cast<__half2*>(&c[mt][nt][1]));
            float v0 = (f0.x + b0) * s0;
            float v1 = (f0.y + b1) * s1;
            float v2 = (f1.x + b0) * s0;
            float v3 = (f1.y + b1) * s1;
            float2 o0 = make_float2(v0 > 0.f ? v0 : alpha * v0,
                                    v1 > 0.f ? v1 : alpha * v1);
            float2 o1 = make_float2(v2 > 0.f ? v2 : alpha * v2,
                                    v3 > 0.f ? v3 : alpha * v3);
            *reinterpret_cast<float2*>(out + (size_t)r0 * COUT + col) = o0;
            *reinterpret_cast<float2*>(out + (size_t)(r0 + 8) * COUT + col) = o1;
        }
    }
}

// ---------------- launch ----------------
extern "C" void kernel_launch(void* const* d_in, const int* in_sizes, int n_in,
                              void* d_out, int out_size) {
    (void)in_sizes; (void)n_in; (void)out_size;
    const float* x     = (const float*)d_in[0];
    const float* gamma = (const float*)d_in[1];
    const float* beta  = (const float*)d_in[2];
    const float* W     = (const float*)d_in[3];
    const float* b     = (const float*)d_in[4];
    const float* scale = (const float*)d_in[5];
    const float* alpha = (const float*)d_in[6];
    float* out = (float*)d_out;

    cudaFuncSetAttribute(k_gemm, cudaFuncAttributeMaxDynamicSharedMemorySize, GEMM_SMEM);

    k_stats_packw<<<NCHUNK + COUT / 4, 256>>>(x, W);   // 1: stats partials + pack W
    k_stats_final<<<CIN / 16, 256>>>(gamma, beta);     // 2: parallel reduction
    k_pack_x<<<NROWS / 4, 256>>>(x);                   // 3
    k_gemm<<<(NROWS / MT) * (COUT / NT), 256, GEMM_SMEM>>>(b, scale, alpha, out);  // 4 <- profiled slot
}